// round 3
// baseline (speedup 1.0000x reference)
#include <cuda_runtime.h>
#include <cstdint>

// Problem constants (fixed by the reference: N=50000, K=32, FN=128, FE=64)
#define NMAX   50048          // 50000 padded to multiple of 128
#define FN     128
#define FE     64
#define KNB    32

// Scratch (device globals: allocation-free per harness rules)
__device__ float g_Wcat[128 * 192];                 // [FN][FE + FN] = [W_qk | wv]
__device__ float g_q2[NMAX * 64];                   // nodes @ (wq @ wk^T)   [N, FE]
__device__ float g_nv[NMAX * 128];                  // nodes @ wv            [N, FN]

// ---------------------------------------------------------------------------
// packed fp32x2 helpers (Blackwell f32x2 pipe: 2 FMA per instruction)
// ---------------------------------------------------------------------------
#define PACK_DUP(o, x) \
    asm("mov.b64 %0, {%1, %1};" : "=l"(o) : "f"(x))
#define FMA2(d, a, b) \
    asm("fma.rn.f32x2 %0, %1, %2, %0;" : "+l"(d) : "l"(a), "l"(b))
#define UNPACK2(lo, hi, v) \
    asm("mov.b64 {%0, %1}, %2;" : "=f"(lo), "=f"(hi) : "l"(v))

// ---------------------------------------------------------------------------
// K0: build Wcat = [ wq @ wk^T (128x64) | wv (128x128) ]
//     W[i][e] = sum_f wq[i,f] * wk[e,f]
// grid = 128 (one block per i-row), 192 threads
// ---------------------------------------------------------------------------
__global__ void k0_wcat(const float* __restrict__ wq,
                        const float* __restrict__ wk,
                        const float* __restrict__ wv) {
    int i = blockIdx.x;
    int t = threadIdx.x;
    __shared__ __align__(16) float s_wq[64];
    if (t < 64) s_wq[t] = wq[i * 64 + t];
    __syncthreads();
    if (t < 64) {
        float s = 0.f;
#pragma unroll 8
        for (int f = 0; f < 64; ++f) s = fmaf(s_wq[f], wk[t * 64 + f], s);
        g_Wcat[i * 192 + t] = s;
    } else {
        int j = t - 64;
        g_Wcat[i * 192 + 64 + j] = wv[i * 128 + j];
    }
}

// ---------------------------------------------------------------------------
// K1: SGEMM  [N,128] @ Wcat[128,192] -> g_q2 (cols 0..63), g_nv (cols 64..191)
// Block tile: 128 rows x 192 cols, 256 threads, thread tile 8r x 12c,
// accumulators packed as f32x2 (col pairs).
// ---------------------------------------------------------------------------
__global__ __launch_bounds__(256) void k1_gemm(const float* __restrict__ nodes,
                                               int N) {
    __shared__ __align__(16) float As[32][128];   // [k][row]  (transposed chunk)
    __shared__ __align__(16) float Bs[32][192];   // [k][col]

    int t  = threadIdx.x;
    int tx = t & 15;          // col group: cols tx*12 .. tx*12+11
    int ty = t >> 4;          // row group: rows ty*8  .. ty*8+7
    int m0 = blockIdx.x * 128;

    unsigned long long acc[8][6];
#pragma unroll
    for (int r = 0; r < 8; ++r)
#pragma unroll
        for (int c = 0; c < 6; ++c) acc[r][c] = 0ull;

    const float4* nodes4 = (const float4*)nodes;
    const float4* w4     = (const float4*)g_Wcat;

    for (int ko = 0; ko < 4; ++ko) {
        __syncthreads();
        // ---- load A chunk [rows m0..m0+127] x [k ko*32..+32], transposed ----
#pragma unroll
        for (int i = 0; i < 4; ++i) {
            int p   = t + i * 256;         // 1024 float4s
            int row = p >> 3;              // 0..127
            int kq  = p & 7;               // float4 index inside 32-k chunk
            int gr  = m0 + row;
            if (gr > N - 1) gr = N - 1;    // clamp (outputs padded anyway)
            float4 v = nodes4[gr * 32 + ko * 8 + kq];
            As[kq * 4 + 0][row] = v.x;
            As[kq * 4 + 1][row] = v.y;
            As[kq * 4 + 2][row] = v.z;
            As[kq * 4 + 3][row] = v.w;
        }
        // ---- load B chunk [k ko*32..+32] x [192] ----
#pragma unroll
        for (int i = 0; i < 6; ++i) {
            int p  = t + i * 256;          // 1536 float4s
            int br = p / 48;
            int bc = p % 48;
            ((float4*)&Bs[br][0])[bc] = w4[(ko * 32 + br) * 48 + bc];
        }
        __syncthreads();

        // ---- accumulate 32 k-steps ----
#pragma unroll 4
        for (int kk = 0; kk < 32; ++kk) {
            float4 al = *(const float4*)&As[kk][ty * 8];
            float4 ah = *(const float4*)&As[kk][ty * 8 + 4];
            unsigned long long a2[8];
            PACK_DUP(a2[0], al.x); PACK_DUP(a2[1], al.y);
            PACK_DUP(a2[2], al.z); PACK_DUP(a2[3], al.w);
            PACK_DUP(a2[4], ah.x); PACK_DUP(a2[5], ah.y);
            PACK_DUP(a2[6], ah.z); PACK_DUP(a2[7], ah.w);

            ulonglong2 b01 = *(const ulonglong2*)&Bs[kk][tx * 12];
            ulonglong2 b23 = *(const ulonglong2*)&Bs[kk][tx * 12 + 4];
            ulonglong2 b45 = *(const ulonglong2*)&Bs[kk][tx * 12 + 8];
            unsigned long long bb[6] = {b01.x, b01.y, b23.x, b23.y, b45.x, b45.y};

#pragma unroll
            for (int r = 0; r < 8; ++r)
#pragma unroll
                for (int c = 0; c < 6; ++c) FMA2(acc[r][c], a2[r], bb[c]);
        }
    }

    // ---- epilogue: cols <64 -> g_q2, cols >=64 -> g_nv (outputs padded) ----
#pragma unroll
    for (int r = 0; r < 8; ++r) {
        int row = m0 + ty * 8 + r;
#pragma unroll
        for (int c = 0; c < 6; ++c) {
            float lo, hi;
            UNPACK2(lo, hi, acc[r][c]);
            int col = tx * 12 + c * 2;
            if (col < 64) {
                *(float2*)&g_q2[row * 64 + col] = make_float2(lo, hi);
            } else {
                *(float2*)&g_nv[row * 128 + (col - 64)] = make_float2(lo, hi);
            }
        }
    }
}

// ---------------------------------------------------------------------------
// K2: per-node logits (edges . q2) * inv_degree, softmax over K, then
//     out[n] = sum_k b_k * g_nv[nlist[n,k]]
// grid = N blocks, 128 threads
// ---------------------------------------------------------------------------
__global__ __launch_bounds__(128) void k2_main(const float* __restrict__ edges,
                                               const int*   __restrict__ nlist,
                                               const float* __restrict__ inv_degree,
                                               float*       __restrict__ out) {
    int n = blockIdx.x;
    int t = threadIdx.x;

    __shared__ __align__(16) float s_q2[64];
    __shared__ float s_l[32];
    __shared__ float s_b[32];
    __shared__ int   s_idx[32];

    if (t < 64) s_q2[t] = g_q2[n * 64 + t];
    if (t >= 64 && t < 96) s_idx[t - 64] = nlist[n * 32 + (t - 64)];
    __syncthreads();

    // ---- logits: 4 threads per k, 16 features each ----
    int k = t >> 2;
    int q = t & 3;
    const float4* e4 = (const float4*)edges + (size_t)n * 512 + k * 16 + q * 4;
    const float4* w4 = (const float4*)&s_q2[q * 16];
    float p = 0.f;
#pragma unroll
    for (int i = 0; i < 4; ++i) {
        float4 e = e4[i];
        float4 w = w4[i];
        p = fmaf(e.x, w.x, p);
        p = fmaf(e.y, w.y, p);
        p = fmaf(e.z, w.z, p);
        p = fmaf(e.w, w.w, p);
    }
    p += __shfl_xor_sync(0xffffffffu, p, 1);
    p += __shfl_xor_sync(0xffffffffu, p, 2);
    float inv = __ldg(&inv_degree[n]);
    if (q == 0) s_l[k] = p * inv;
    __syncthreads();

    // ---- softmax over K=32 in warp 0 ----
    if (t < 32) {
        float l = s_l[t];
        float m = l;
#pragma unroll
        for (int o = 16; o; o >>= 1) m = fmaxf(m, __shfl_xor_sync(0xffffffffu, m, o));
        float e = __expf(l - m);
        float s = e;
#pragma unroll
        for (int o = 16; o; o >>= 1) s += __shfl_xor_sync(0xffffffffu, s, o);
        s_b[t] = e / s;
    }
    __syncthreads();

    // ---- weighted gather: thread t owns output feature t ----
    float a0 = 0.f, a1 = 0.f, a2 = 0.f, a3 = 0.f;
#pragma unroll
    for (int kk = 0; kk < 32; kk += 4) {
        a0 = fmaf(s_b[kk + 0], g_nv[s_idx[kk + 0] * 128 + t], a0);
        a1 = fmaf(s_b[kk + 1], g_nv[s_idx[kk + 1] * 128 + t], a1);
        a2 = fmaf(s_b[kk + 2], g_nv[s_idx[kk + 2] * 128 + t], a2);
        a3 = fmaf(s_b[kk + 3], g_nv[s_idx[kk + 3] * 128 + t], a3);
    }
    out[(size_t)n * 128 + t] = (a0 + a1) + (a2 + a3);
}

// ---------------------------------------------------------------------------
// Inputs (metadata order): nodes f32[N,128], nlist i32[N,32], edges f32[N,32,64],
//                          inv_degree f32[N], wq f32[128,64], wk f32[64,64],
//                          wv f32[128,128]
// Output: f32[N,128]
// ---------------------------------------------------------------------------
extern "C" void kernel_launch(void* const* d_in, const int* in_sizes, int n_in,
                              void* d_out, int out_size) {
    const float* nodes      = (const float*)d_in[0];
    const int*   nlist      = (const int*)  d_in[1];
    const float* edges      = (const float*)d_in[2];
    const float* inv_degree = (const float*)d_in[3];
    const float* wq         = (const float*)d_in[4];
    const float* wk         = (const float*)d_in[5];
    const float* wv         = (const float*)d_in[6];
    float*       out        = (float*)d_out;

    int N = in_sizes[0] / FN;   // 50000

    k0_wcat<<<128, 192>>>(wq, wk, wv);
    k1_gemm<<<(N + 127) / 128, 256>>>(nodes, N);
    k2_main<<<N, 128>>>(edges, nlist, inv_degree, out);
}

// round 5
// speedup vs baseline: 1.1339x; 1.1339x over previous
#include <cuda_runtime.h>
#include <cuda_fp16.h>
#include <cstdint>

// Problem constants (fixed by the reference: N=50000, K=32, FN=128, FE=64)
#define NMAX   50048          // 50000 padded to multiple of 128
#define FN     128
#define FE     64

// Scratch (device globals: allocation-free per harness rules)
__device__ float  g_Wqk[128 * 64];        // wq @ wk^T
__device__ float  g_q2[NMAX * 64];        // nodes @ (wq @ wk^T)   [N, FE] fp32
__device__ __half g_nv[NMAX * 128];       // nodes @ wv            [N, FN] fp16

// ---------------------------------------------------------------------------
// packed fp32x2 helpers
// ---------------------------------------------------------------------------
#define PACK_DUP(o, x) \
    asm("mov.b64 %0, {%1, %1};" : "=l"(o) : "f"(x))
#define FMA2(d, a, b) \
    asm("fma.rn.f32x2 %0, %1, %2, %0;" : "+l"(d) : "l"(a), "l"(b))
#define UNPACK2(lo, hi, v) \
    asm("mov.b64 {%0, %1}, %2;" : "=f"(lo), "=f"(hi) : "l"(v))

// ---------------------------------------------------------------------------
// K0: Wqk[i][e] = sum_f wq[i,f] * wk[e,f]    (128x64 outputs)
// grid = 64 blocks x 128 threads; block b covers rows i = 2b, 2b+1
// ---------------------------------------------------------------------------
__global__ void k0_wqk(const float* __restrict__ wq,
                       const float* __restrict__ wk) {
    int t = threadIdx.x;
    int i0 = blockIdx.x * 2;
    __shared__ __align__(16) float s_wq[2][64];
    s_wq[t >> 6][t & 63] = wq[i0 * 64 + t];
    __syncthreads();
    int e = t & 63;
    int i = i0 + (t >> 6);
    const float* wkr = wk + e * 64;
    const float* qr  = s_wq[t >> 6];
    float s = 0.f;
#pragma unroll 16
    for (int f = 0; f < 64; ++f) s = fmaf(qr[f], wkr[f], s);
    g_Wqk[i * 64 + e] = s;
}

// ---------------------------------------------------------------------------
// K1: SGEMM  [N,128] @ [Wqk | wv][128,192] -> g_q2 (fp32), g_nv (fp16)
// Block tile: 128 rows x 192 cols, 256 threads, thread tile 8r x 12c (f32x2)
// ---------------------------------------------------------------------------
__global__ __launch_bounds__(256) void k1_gemm(const float* __restrict__ nodes,
                                               const float* __restrict__ wv,
                                               int N) {
    __shared__ __align__(16) float As[32][128];   // [k][row]
    __shared__ __align__(16) float Bs[32][192];   // [k][col]

    int t  = threadIdx.x;
    int tx = t & 15;          // col group: cols tx*12 .. +11
    int ty = t >> 4;          // row group: rows ty*8  .. +7
    int m0 = blockIdx.x * 128;

    unsigned long long acc[8][6];
#pragma unroll
    for (int r = 0; r < 8; ++r)
#pragma unroll
        for (int c = 0; c < 6; ++c) acc[r][c] = 0ull;

    const float4* nodes4 = (const float4*)nodes;
    const float4* wqk4   = (const float4*)g_Wqk;
    const float4* wv4    = (const float4*)wv;

    for (int ko = 0; ko < 4; ++ko) {
        __syncthreads();
        // A chunk [128 rows] x [32 k], transposed into As[k][row]
#pragma unroll
        for (int i = 0; i < 4; ++i) {
            int p   = t + i * 256;
            int row = p >> 3;
            int kq  = p & 7;
            int gr  = m0 + row;
            if (gr > N - 1) gr = N - 1;
            float4 v = nodes4[gr * 32 + ko * 8 + kq];
            As[kq * 4 + 0][row] = v.x;
            As[kq * 4 + 1][row] = v.y;
            As[kq * 4 + 2][row] = v.z;
            As[kq * 4 + 3][row] = v.w;
        }
        // B chunk: cols 0..63 from g_Wqk, cols 64..191 from wv
#pragma unroll
        for (int i = 0; i < 6; ++i) {
            int p  = t + i * 256;          // 1536 float4 slots
            int br = p / 48;               // k-row 0..31
            int bc = p % 48;               // float4 col 0..47
            int gk = ko * 32 + br;
            float4 v = (bc < 16) ? wqk4[gk * 16 + bc]
                                 : wv4[gk * 32 + (bc - 16)];
            ((float4*)&Bs[br][0])[bc] = v;
        }
        __syncthreads();

#pragma unroll 4
        for (int kk = 0; kk < 32; ++kk) {
            float4 al = *(const float4*)&As[kk][ty * 8];
            float4 ah = *(const float4*)&As[kk][ty * 8 + 4];
            unsigned long long a2[8];
            PACK_DUP(a2[0], al.x); PACK_DUP(a2[1], al.y);
            PACK_DUP(a2[2], al.z); PACK_DUP(a2[3], al.w);
            PACK_DUP(a2[4], ah.x); PACK_DUP(a2[5], ah.y);
            PACK_DUP(a2[6], ah.z); PACK_DUP(a2[7], ah.w);

            ulonglong2 b01 = *(const ulonglong2*)&Bs[kk][tx * 12];
            ulonglong2 b23 = *(const ulonglong2*)&Bs[kk][tx * 12 + 4];
            ulonglong2 b45 = *(const ulonglong2*)&Bs[kk][tx * 12 + 8];
            unsigned long long bb[6] = {b01.x, b01.y, b23.x, b23.y, b45.x, b45.y};

#pragma unroll
            for (int r = 0; r < 8; ++r)
#pragma unroll
                for (int c = 0; c < 6; ++c) FMA2(acc[r][c], a2[r], bb[c]);
        }
    }

    // epilogue: cols <64 -> g_q2 fp32 ; cols >=64 -> g_nv fp16
#pragma unroll
    for (int r = 0; r < 8; ++r) {
        int row = m0 + ty * 8 + r;
#pragma unroll
        for (int c = 0; c < 6; ++c) {
            float lo, hi;
            UNPACK2(lo, hi, acc[r][c]);
            int col = tx * 12 + c * 2;
            if (col < 64) {
                *(float2*)&g_q2[row * 64 + col] = make_float2(lo, hi);
            } else {
                __half2 h = __float22half2_rn(make_float2(lo, hi));
                *(__half2*)&g_nv[row * 128 + (col - 64)] = h;
            }
        }
    }
}

// ---------------------------------------------------------------------------
// K2: logits (edges . q2) * inv_degree, softmax over K=32,
//     out[n] = sum_k b_k * g_nv[nlist[n,k]]   (fp16 gather, fp32 accum)
// grid = N blocks, 128 threads
// ---------------------------------------------------------------------------
__global__ __launch_bounds__(128) void k2_main(const float* __restrict__ edges,
                                               const int*   __restrict__ nlist,
                                               const float* __restrict__ inv_degree,
                                               float*       __restrict__ out) {
    int n = blockIdx.x;
    int t = threadIdx.x;
    int w = t >> 5;           // warp 0..3
    int l = t & 31;           // lane

    __shared__ __align__(16) float s_q2[64];
    __shared__ float s_l[32];
    __shared__ float s_b[32];
    __shared__ int   s_idx[32];
    __shared__ __align__(16) float s_red[4][128];

    if (t < 64) s_q2[t] = g_q2[n * 64 + t];
    if (t >= 64 && t < 96) s_idx[t - 64] = nlist[n * 32 + (t - 64)];
    __syncthreads();

    // ---- logits: 4 threads per k, 16 features each (streaming edge loads) ----
    {
        int k = t >> 2;
        int q = t & 3;
        const float4* e4 = (const float4*)edges + (size_t)n * 512 + k * 16 + q * 4;
        const float4* w4 = (const float4*)&s_q2[q * 16];
        float p = 0.f;
#pragma unroll
        for (int i = 0; i < 4; ++i) {
            float4 e = __ldcs(&e4[i]);
            float4 wv_ = w4[i];
            p = fmaf(e.x, wv_.x, p);
            p = fmaf(e.y, wv_.y, p);
            p = fmaf(e.z, wv_.z, p);
            p = fmaf(e.w, wv_.w, p);
        }
        p += __shfl_xor_sync(0xffffffffu, p, 1);
        p += __shfl_xor_sync(0xffffffffu, p, 2);
        float inv = __ldg(&inv_degree[n]);
        if (q == 0) s_l[k] = p * inv;
    }
    __syncthreads();

    // ---- softmax over K=32 in warp 0 ----
    if (t < 32) {
        float lg = s_l[t];
        float m = lg;
#pragma unroll
        for (int o = 16; o; o >>= 1) m = fmaxf(m, __shfl_xor_sync(0xffffffffu, m, o));
        float e = __expf(lg - m);
        float s = e;
#pragma unroll
        for (int o = 16; o; o >>= 1) s += __shfl_xor_sync(0xffffffffu, s, o);
        s_b[t] = e / s;
    }
    __syncthreads();

    // ---- weighted fp16 gather: warp w handles k in [w*8, w*8+8),
    //      lane l loads 8B = 4 features (cols 4l..4l+3) ----
    float4 acc = make_float4(0.f, 0.f, 0.f, 0.f);
#pragma unroll
    for (int kk = 0; kk < 8; ++kk) {
        int  ki  = w * 8 + kk;
        int  row = s_idx[ki];
        float bw = s_b[ki];
        uint2 v = *(const uint2*)&g_nv[(size_t)row * 128 + l * 4];
        float2 f0 = __half22float2(*(__half2*)&v.x);
        float2 f1 = __half22float2(*(__half2*)&v.y);
        acc.x = fmaf(bw, f0.x, acc.x);
        acc.y = fmaf(bw, f0.y, acc.y);
        acc.z = fmaf(bw, f1.x, acc.z);
        acc.w = fmaf(bw, f1.y, acc.w);
    }
    *(float4*)&s_red[w][l * 4] = acc;
    __syncthreads();

    // ---- cross-warp reduce + store ----
    float r0 = s_red[0][t] + s_red[1][t];
    float r1 = s_red[2][t] + s_red[3][t];
    __stcs(&out[(size_t)n * 128 + t], r0 + r1);
}

// ---------------------------------------------------------------------------
// Inputs (metadata order): nodes f32[N,128], nlist i32[N,32], edges f32[N,32,64],
//                          inv_degree f32[N], wq f32[128,64], wk f32[64,64],
//                          wv f32[128,128]
// Output: f32[N,128]
// ---------------------------------------------------------------------------
extern "C" void kernel_launch(void* const* d_in, const int* in_sizes, int n_in,
                              void* d_out, int out_size) {
    const float* nodes      = (const float*)d_in[0];
    const int*   nlist      = (const int*)  d_in[1];
    const float* edges      = (const float*)d_in[2];
    const float* inv_degree = (const float*)d_in[3];
    const float* wq         = (const float*)d_in[4];
    const float* wk         = (const float*)d_in[5];
    const float* wv         = (const float*)d_in[6];
    float*       out        = (float*)d_out;

    int N = in_sizes[0] / FN;   // 50000

    k0_wqk<<<64, 128>>>(wq, wk);
    k1_gemm<<<(N + 127) / 128, 256>>>(nodes, wv, N);
    k2_main<<<N, 128>>>(edges, nlist, inv_degree, out);
}